// round 13
// baseline (speedup 1.0000x reference)
#include <cuda_runtime.h>
#include <math.h>

#define NN 50000
#define EE 800000
#define FIN 256
#define CC 32
#define HH 4
#define HCC 128
#define LEPS 1e-5f
#define SLOPE 0.2f

// ---------------- scratch (no allocs allowed) ----------------
__device__ float d_xl[NN * HCC];      // lin_l(h)
__device__ float d_xr[NN * HCC];      // lin_r(h)
__device__ float d_gat[NN * HCC];     // GAT aggregation output
__device__ double d_red[2];           // global sum / sumsq (self-resetting)
__device__ unsigned int d_ctr;        // block-completion counter (self-resetting)
__device__ float d_stats[2];          // mu, rstd for graph-LN
// CSR by destination
__device__ int  d_cnt[NN];            // zero at load; k_scan re-zeros for replay
__device__ int  d_rowoff[NN + 1];
__device__ int  d_cursor[NN];
__device__ int2 d_csr[EE];            // (src, ea as bits)

// ---------------- helpers ----------------
__device__ __forceinline__ float wsum(float v) {
    #pragma unroll
    for (int o = 16; o; o >>= 1) v += __shfl_xor_sync(0xFFFFFFFFu, v, o);
    return v;
}
__device__ __forceinline__ float lrelu(float z) {
    return z > 0.0f ? z : SLOPE * z;
}
// per-8-lane-group sum (head groups)
__device__ __forceinline__ float hred8(float v) {
    v += __shfl_xor_sync(0xFFFFFFFFu, v, 1);
    v += __shfl_xor_sync(0xFFFFFFFFu, v, 2);
    v += __shfl_xor_sync(0xFFFFFFFFu, v, 4);
    return v;
}

// ---------------- CSR build ----------------
__global__ void k_hist(const int* __restrict__ dst) {
    int e = blockIdx.x * blockDim.x + threadIdx.x;
    if (e < EE) atomicAdd(&d_cnt[dst[e]], 1);
}
// single block, 1024 threads: exclusive scan of d_cnt -> d_rowoff, d_cursor.
// Re-zeros d_cnt for the next launch (graph replay).
__global__ void k_scan() {
    __shared__ int wsum_ex[32];
    __shared__ int s_total;
    int lane = threadIdx.x & 31, wid = threadIdx.x >> 5;
    int carry = 0;
    const int CH = (NN + 1023) / 1024;
    for (int c = 0; c < CH; c++) {
        int i = c * 1024 + threadIdx.x;
        int v = (i < NN) ? d_cnt[i] : 0;
        if (i < NN) d_cnt[i] = 0;
        int inc = v;
        #pragma unroll
        for (int o = 1; o < 32; o <<= 1) {
            int t = __shfl_up_sync(0xFFFFFFFFu, inc, o);
            if (lane >= o) inc += t;
        }
        if (lane == 31) wsum_ex[wid] = inc;
        __syncthreads();
        if (wid == 0) {
            int w = wsum_ex[lane];
            int wi = w;
            #pragma unroll
            for (int o = 1; o < 32; o <<= 1) {
                int t = __shfl_up_sync(0xFFFFFFFFu, wi, o);
                if (lane >= o) wi += t;
            }
            wsum_ex[lane] = wi - w;
            if (lane == 31) s_total = wi;
        }
        __syncthreads();
        int excl = carry + wsum_ex[wid] + (inc - v);
        if (i < NN) { d_rowoff[i] = excl; d_cursor[i] = excl; }
        carry += s_total;
        __syncthreads();
    }
    if (threadIdx.x == 0) d_rowoff[NN] = EE;
}
__global__ void k_scatter(const int* __restrict__ src, const int* __restrict__ dst,
                          const float* __restrict__ ea) {
    int e = blockIdx.x * blockDim.x + threadIdx.x;
    if (e >= EE) return;
    int d = dst[e];
    int pos = atomicAdd(&d_cursor[d], 1);
    d_csr[pos] = make_int2(src[e], __float_as_int(ea[e]));
}

// ---------------- K1: embed GEMM + node LN + ReLU + JK init + layer-0 lin_l/lin_r ----------------
// 256 threads; col = lane; each warp computes 4 nodes; then computes xl/xr for layer 0
// via shfl-broadcast of h and smem weights (removes the separate linlr kernel + d_h).
__global__ void __launch_bounds__(256)
k_embed(const float* __restrict__ x, const float* __restrict__ W,
        const float* __restrict__ b, const float* __restrict__ lw,
        const float* __restrict__ lb,
        const float* __restrict__ Wl0, const float* __restrict__ bl0,
        const float* __restrict__ Wr0, const float* __restrict__ br0,
        float* __restrict__ out) {
    __shared__ float sWT[CC][FIN + 4];   // W transposed, padded
    __shared__ float sWl[CC][HCC];       // 16 KB
    __shared__ float sWr[CC][HCC];       // 16 KB
    int tid = threadIdx.x;
    for (int i = tid; i < FIN * CC; i += 256) {
        int k = i >> 5, col = i & 31;
        sWT[col][k] = W[i];
    }
    for (int i = tid; i < CC * HCC; i += 256) {
        sWl[i >> 7][i & 127] = Wl0[i];
        sWr[i >> 7][i & 127] = Wr0[i];
    }
    __syncthreads();
    int lane = tid & 31;
    int warp = tid >> 5;
    int n0 = blockIdx.x * 32 + warp * 4;

    float bv = b[lane];
    float acc0 = bv, acc1 = bv, acc2 = bv, acc3 = bv;
    bool ok0 = n0 + 0 < NN, ok1 = n0 + 1 < NN, ok2 = n0 + 2 < NN, ok3 = n0 + 3 < NN;
    const float4* x0 = (const float4*)(x + (size_t)(n0 + 0) * FIN);
    const float4* x1 = (const float4*)(x + (size_t)(n0 + 1) * FIN);
    const float4* x2 = (const float4*)(x + (size_t)(n0 + 2) * FIN);
    const float4* x3 = (const float4*)(x + (size_t)(n0 + 3) * FIN);

    #pragma unroll 4
    for (int kq = 0; kq < FIN / 4; kq++) {
        float4 w4 = *(const float4*)&sWT[lane][kq * 4];
        if (ok0) { float4 v = __ldg(&x0[kq]); acc0 += v.x*w4.x + v.y*w4.y + v.z*w4.z + v.w*w4.w; }
        if (ok1) { float4 v = __ldg(&x1[kq]); acc1 += v.x*w4.x + v.y*w4.y + v.z*w4.z + v.w*w4.w; }
        if (ok2) { float4 v = __ldg(&x2[kq]); acc2 += v.x*w4.x + v.y*w4.y + v.z*w4.z + v.w*w4.w; }
        if (ok3) { float4 v = __ldg(&x3[kq]); acc3 += v.x*w4.x + v.y*w4.y + v.z*w4.z + v.w*w4.w; }
    }

    float lwv = lw[lane], lbv = lb[lane];
    float4 bl4 = *(const float4*)&bl0[lane * 4];
    float4 br4 = *(const float4*)&br0[lane * 4];
    float accs[4] = {acc0, acc1, acc2, acc3};
    #pragma unroll
    for (int m = 0; m < 4; m++) {
        int n = n0 + m;
        if (n >= NN) break;   // warp-uniform
        float a = accs[m];
        float mu = wsum(a) * (1.0f / CC);
        float c = a - mu;
        float var = wsum(c * c) * (1.0f / CC);
        float y = c * rsqrtf(var + LEPS) * lwv + lbv;
        y = fmaxf(y, 0.0f);
        out[n * CC + lane] = y;   // JK running max init

        // layer-0 xl/xr for this node: lane owns cols [lane*4, lane*4+4)
        float4 xl4 = bl4, xr4 = br4;
        #pragma unroll
        for (int k = 0; k < CC; k++) {
            float hk = __shfl_sync(0xFFFFFFFFu, y, k);
            float4 wl = *(const float4*)&sWl[k][lane * 4];
            float4 wr = *(const float4*)&sWr[k][lane * 4];
            xl4.x += hk * wl.x; xl4.y += hk * wl.y; xl4.z += hk * wl.z; xl4.w += hk * wl.w;
            xr4.x += hk * wr.x; xr4.y += hk * wr.y; xr4.z += hk * wr.z; xr4.w += hk * wr.w;
        }
        *(float4*)&d_xl[(size_t)n * HCC + lane * 4] = xl4;
        *(float4*)&d_xr[(size_t)n * HCC + lane * 4] = xr4;
    }
}

// ---------------- K3: fused GATv2 aggregation + graph-LN reduction ----------------
// warp per dst node; fixed-reference softmax (self logit p); depth-2 pipeline.
__global__ void k_gat(const float* __restrict__ We, const float* __restrict__ att,
                      const float* __restrict__ gb) {
    int tid = threadIdx.x;
    int lane = tid & 31;
    int w = tid >> 5;
    int n = blockIdx.x * 8 + w;

    float4 xr4  = *(const float4*)&d_xr[(size_t)n * HCC + lane * 4];
    float4 xls  = *(const float4*)&d_xl[(size_t)n * HCC + lane * 4];
    float4 att4 = *(const float4*)&att[lane * 4];
    float4 We4  = *(const float4*)&We[lane * 4];

    // self loop logit p (edge_attr = 0)
    float p;
    {
        float zx = lrelu(xls.x + xr4.x);
        float zy = lrelu(xls.y + xr4.y);
        float zz = lrelu(xls.z + xr4.z);
        float zw = lrelu(xls.w + xr4.w);
        p = hred8(zx * att4.x + zy * att4.y + zz * att4.z + zw * att4.w);
    }
    float s = 1.0f;       // exp(p-p)
    float4 acc = xls;     // self message

    int beg = __ldg(&d_rowoff[n]), end = __ldg(&d_rowoff[n + 1]);

    // depth-2 software pipeline
    int2 e0 = make_int2(0, 0), e1 = make_int2(0, 0);
    float4 x0 = make_float4(0.f, 0.f, 0.f, 0.f), x1 = x0;
    if (beg < end) {
        e0 = __ldg(&d_csr[beg]);
        x0 = *(const float4*)&d_xl[(size_t)e0.x * HCC + lane * 4];
    }
    if (beg + 1 < end) {
        e1 = __ldg(&d_csr[beg + 1]);
        x1 = *(const float4*)&d_xl[(size_t)e1.x * HCC + lane * 4];
    }
    for (int k = beg; k < end; k++) {
        int2 ec = e0;
        float4 xc = x0;
        e0 = e1; x0 = x1;
        if (k + 2 < end) {
            e1 = __ldg(&d_csr[k + 2]);
            x1 = *(const float4*)&d_xl[(size_t)e1.x * HCC + lane * 4];
        }
        float eaf = __int_as_float(ec.y);
        float zx = lrelu(xc.x + xr4.x + eaf * We4.x);
        float zy = lrelu(xc.y + xr4.y + eaf * We4.y);
        float zz = lrelu(xc.z + xr4.z + eaf * We4.z);
        float zw = lrelu(xc.w + xr4.w + eaf * We4.w);
        float q = hred8(zx * att4.x + zy * att4.y + zz * att4.z + zw * att4.w);
        float ex = __expf(q - p);
        s += ex;
        acc.x += ex * xc.x;
        acc.y += ex * xc.y;
        acc.z += ex * xc.z;
        acc.w += ex * xc.w;
    }
    float inv = 1.0f / s;
    float4 o;
    o.x = acc.x * inv; o.y = acc.y * inv; o.z = acc.z * inv; o.w = acc.w * inv;
    *(float4*)&d_gat[(size_t)n * HCC + lane * 4] = o;

    // ---- fused graph-LN reduction (over o + gb) ----
    float4 gb4 = *(const float4*)&gb[lane * 4];
    float vx = o.x + gb4.x, vy = o.y + gb4.y, vz = o.z + gb4.z, vw = o.w + gb4.w;
    double s0 = (double)vx + (double)vy + (double)vz + (double)vw;
    double s1 = (double)vx * vx + (double)vy * vy + (double)vz * vz + (double)vw * vw;
    #pragma unroll
    for (int off = 16; off; off >>= 1) {
        s0 += __shfl_xor_sync(0xFFFFFFFFu, s0, off);
        s1 += __shfl_xor_sync(0xFFFFFFFFu, s1, off);
    }
    __shared__ double sh0[8], sh1[8];
    if (lane == 0) { sh0[w] = s0; sh1[w] = s1; }
    __syncthreads();
    if (w == 0) {
        s0 = (lane < 8) ? sh0[lane] : 0.0;
        s1 = (lane < 8) ? sh1[lane] : 0.0;
        #pragma unroll
        for (int off = 4; off; off >>= 1) {
            s0 += __shfl_xor_sync(0xFFFFFFFFu, s0, off);
            s1 += __shfl_xor_sync(0xFFFFFFFFu, s1, off);
        }
        if (lane == 0) {
            atomicAdd(&d_red[0], s0);
            atomicAdd(&d_red[1], s1);
            __threadfence();
            unsigned int t = atomicAdd(&d_ctr, 1u);
            if (t == gridDim.x - 1) {
                double inv2 = 1.0 / ((double)NN * (double)HCC);
                double mu = d_red[0] * inv2;
                double var = d_red[1] * inv2 - mu * mu;
                d_stats[0] = (float)mu;
                d_stats[1] = (float)(1.0 / sqrt(var + 1e-5));
                d_red[0] = 0.0;
                d_red[1] = 0.0;
                d_ctr = 0u;
            }
        }
    }
}

// ---------------- K8: graph-LN apply + ReLU + 128->32 GEMM + node LN + ReLU + JK max
//                  + (hasNext) next-layer lin_l/lin_r ----------------
__global__ void k_lin2(const float* __restrict__ gb, const float* __restrict__ l1w,
                       const float* __restrict__ l1b, const float* __restrict__ lw,
                       const float* __restrict__ lb, const float* __restrict__ l2w,
                       const float* __restrict__ l2b,
                       const float* __restrict__ Wln, const float* __restrict__ bln,
                       const float* __restrict__ Wrn, const float* __restrict__ brn,
                       int hasNext, float* __restrict__ out) {
    __shared__ float s_lw[HCC * CC];   // 16 KB
    __shared__ float sWl[CC][HCC];     // 16 KB (next-layer lin_l)
    __shared__ float sWr[CC][HCC];     // 16 KB (next-layer lin_r)
    int tid = threadIdx.x;
    for (int i = tid; i < HCC * CC; i += 256) s_lw[i] = lw[i];
    if (hasNext) {
        for (int i = tid; i < CC * HCC; i += 256) {
            sWl[i >> 7][i & 127] = Wln[i];
            sWr[i >> 7][i & 127] = Wrn[i];
        }
    }
    __syncthreads();
    int lane = tid & 31;
    int n = blockIdx.x * 8 + (tid >> 5);
    float mu = d_stats[0], rstd = d_stats[1];
    float4 g4  = *(const float4*)&d_gat[(size_t)n * HCC + lane * 4];
    float4 gb4 = *(const float4*)&gb[lane * 4];
    float4 w14 = *(const float4*)&l1w[lane * 4];
    float4 b14 = *(const float4*)&l1b[lane * 4];
    float4 v4;
    v4.x = fmaxf((g4.x + gb4.x - mu) * rstd * w14.x + b14.x, 0.0f);
    v4.y = fmaxf((g4.y + gb4.y - mu) * rstd * w14.y + b14.y, 0.0f);
    v4.z = fmaxf((g4.z + gb4.z - mu) * rstd * w14.z + b14.z, 0.0f);
    v4.w = fmaxf((g4.w + gb4.w - mu) * rstd * w14.w + b14.w, 0.0f);
    float acc = lb[lane];
    #pragma unroll
    for (int j = 0; j < 32; j++) {
        float vx = __shfl_sync(0xFFFFFFFFu, v4.x, j);
        float vy = __shfl_sync(0xFFFFFFFFu, v4.y, j);
        float vz = __shfl_sync(0xFFFFFFFFu, v4.z, j);
        float vw = __shfl_sync(0xFFFFFFFFu, v4.w, j);
        int k = j * 4;
        acc += vx * s_lw[k * CC + lane];
        acc += vy * s_lw[(k + 1) * CC + lane];
        acc += vz * s_lw[(k + 2) * CC + lane];
        acc += vw * s_lw[(k + 3) * CC + lane];
    }
    float m2 = wsum(acc) * (1.0f / CC);
    float c = acc - m2;
    float var = wsum(c * c) * (1.0f / CC);
    float y = c * rsqrtf(var + LEPS) * l2w[lane] + l2b[lane];
    y = fmaxf(y, 0.0f);
    out[n * CC + lane] = fmaxf(out[n * CC + lane], y);   // JK max

    if (hasNext) {
        float4 xl4 = *(const float4*)&bln[lane * 4];
        float4 xr4 = *(const float4*)&brn[lane * 4];
        #pragma unroll
        for (int k = 0; k < CC; k++) {
            float hk = __shfl_sync(0xFFFFFFFFu, y, k);
            float4 wl = *(const float4*)&sWl[k][lane * 4];
            float4 wr = *(const float4*)&sWr[k][lane * 4];
            xl4.x += hk * wl.x; xl4.y += hk * wl.y; xl4.z += hk * wl.z; xl4.w += hk * wl.w;
            xr4.x += hk * wr.x; xr4.y += hk * wr.y; xr4.z += hk * wr.z; xr4.w += hk * wr.w;
        }
        *(float4*)&d_xl[(size_t)n * HCC + lane * 4] = xl4;
        *(float4*)&d_xr[(size_t)n * HCC + lane * 4] = xr4;
    }
}

// ---------------- host ----------------
extern "C" void kernel_launch(void* const* d_in, const int* in_sizes, int n_in,
                              void* d_out, int out_size) {
    const float* x     = (const float*)d_in[0];
    const int*   ei    = (const int*)d_in[1];
    const float* ea    = (const float*)d_in[2];
    const float* W_emb = (const float*)d_in[3];
    const float* b_emb = (const float*)d_in[4];
    const float* ln0w  = (const float*)d_in[5];
    const float* ln0b  = (const float*)d_in[6];
    const float* Wl    = (const float*)d_in[7];
    const float* bl    = (const float*)d_in[8];
    const float* Wr    = (const float*)d_in[9];
    const float* br    = (const float*)d_in[10];
    const float* We    = (const float*)d_in[11];
    const float* att   = (const float*)d_in[12];
    const float* gatb  = (const float*)d_in[13];
    const float* ln1w  = (const float*)d_in[14];
    const float* ln1b  = (const float*)d_in[15];
    const float* linw  = (const float*)d_in[16];
    const float* linb  = (const float*)d_in[17];
    const float* ln2w  = (const float*)d_in[18];
    const float* ln2b  = (const float*)d_in[19];

    const int* src = ei;
    const int* dst = ei + EE;
    float* out = (float*)d_out;

    const int gatBlocks   = NN / 8;            // 6250, exact
    const int embedBlocks = (NN + 31) / 32;    // 1563

    // CSR build: 3 launches; k_scan re-zeros d_cnt for graph replay
    k_hist<<<(EE + 255) / 256, 256>>>(dst);             // launch 0
    k_scan<<<1, 1024>>>();                              // launch 1
    k_scatter<<<(EE + 255) / 256, 256>>>(src, dst, ea); // launch 2

    // launch 3 (profiled window): fused embed + layer-0 lin_l/lin_r
    k_embed<<<embedBlocks, 256>>>(x, W_emb, b_emb, ln0w, ln0b,
                                  Wl, bl, Wr, br, out);

    for (int l = 0; l < 2; l++) {
        const float* We_l  = We + l * HCC;
        const float* att_l = att + l * HH * CC;
        const float* gb_l  = gatb + l * HCC;
        const float* l1w_l = ln1w + l * HCC;
        const float* l1b_l = ln1b + l * HCC;
        const float* lw_l  = linw + l * HCC * CC;
        const float* lb_l  = linb + l * CC;
        const float* l2w_l = ln2w + l * CC;
        const float* l2b_l = ln2b + l * CC;
        int hasNext = (l + 1 < 2);
        const float* Wln = Wl + (l + hasNext) * CC * HCC;
        const float* bln = bl + (l + hasNext) * HCC;
        const float* Wrn = Wr + (l + hasNext) * CC * HCC;
        const float* brn = br + (l + hasNext) * HCC;

        k_gat<<<gatBlocks, 256>>>(We_l, att_l, gb_l);
        k_lin2<<<gatBlocks, 256>>>(gb_l, l1w_l, l1b_l, lw_l, lb_l, l2w_l, l2b_l,
                                   Wln, bln, Wrn, brn, hasNext, out);
    }
}

// round 15
// speedup vs baseline: 1.6821x; 1.6821x over previous
#include <cuda_runtime.h>
#include <math.h>

#define NN 50000
#define EE 800000
#define FIN 256
#define CC 32
#define HH 4
#define HCC 128
#define LEPS 1e-5f
#define SLOPE 0.2f

// ---------------- scratch (no allocs allowed) ----------------
__device__ float d_h[NN * CC];        // current node features
__device__ float d_xl[NN * HCC];      // lin_l(h)
__device__ float d_xr[NN * HCC];      // lin_r(h)
__device__ float d_gat[NN * HCC];     // GAT aggregation output
__device__ double d_red[2];           // global sum / sumsq (self-resetting)
__device__ unsigned int d_ctr;        // block-completion counter (self-resetting)
__device__ float d_stats[2];          // mu, rstd for graph-LN
// CSR by destination
__device__ int  d_cnt[NN];            // zero at load; k_scan re-zeros for replay
__device__ int  d_rowoff[NN + 1];
__device__ int  d_cursor[NN];
__device__ int2 d_csr[EE];            // (src, ea as bits)

// ---------------- helpers ----------------
__device__ __forceinline__ float wsum(float v) {
    #pragma unroll
    for (int o = 16; o; o >>= 1) v += __shfl_xor_sync(0xFFFFFFFFu, v, o);
    return v;
}
__device__ __forceinline__ float lrelu(float z) {
    return z > 0.0f ? z : SLOPE * z;
}

// ---------------- CSR build ----------------
__global__ void k_hist(const int* __restrict__ dst) {
    int e = blockIdx.x * blockDim.x + threadIdx.x;
    if (e < EE) atomicAdd(&d_cnt[dst[e]], 1);
}
// single block, 1024 threads: exclusive scan of d_cnt -> d_rowoff, d_cursor.
// Re-zeros d_cnt for the next launch (graph replay).
__global__ void k_scan() {
    __shared__ int wsum_ex[32];
    __shared__ int s_total;
    int lane = threadIdx.x & 31, wid = threadIdx.x >> 5;
    int carry = 0;
    const int CH = (NN + 1023) / 1024;
    for (int c = 0; c < CH; c++) {
        int i = c * 1024 + threadIdx.x;
        int v = (i < NN) ? d_cnt[i] : 0;
        if (i < NN) d_cnt[i] = 0;
        int inc = v;
        #pragma unroll
        for (int o = 1; o < 32; o <<= 1) {
            int t = __shfl_up_sync(0xFFFFFFFFu, inc, o);
            if (lane >= o) inc += t;
        }
        if (lane == 31) wsum_ex[wid] = inc;
        __syncthreads();
        if (wid == 0) {
            int w = wsum_ex[lane];
            int wi = w;
            #pragma unroll
            for (int o = 1; o < 32; o <<= 1) {
                int t = __shfl_up_sync(0xFFFFFFFFu, wi, o);
                if (lane >= o) wi += t;
            }
            wsum_ex[lane] = wi - w;
            if (lane == 31) s_total = wi;
        }
        __syncthreads();
        int excl = carry + wsum_ex[wid] + (inc - v);
        if (i < NN) { d_rowoff[i] = excl; d_cursor[i] = excl; }
        carry += s_total;
        __syncthreads();
    }
    if (threadIdx.x == 0) d_rowoff[NN] = EE;
}
__global__ void k_scatter(const int* __restrict__ src, const int* __restrict__ dst,
                          const float* __restrict__ ea) {
    int e = blockIdx.x * blockDim.x + threadIdx.x;
    if (e >= EE) return;
    int d = dst[e];
    int pos = atomicAdd(&d_cursor[d], 1);
    d_csr[pos] = make_int2(src[e], __float_as_int(ea[e]));
}

// ---------------- K1: embed GEMM + node LN + ReLU + JK init ----------------
// Register-tiled: 256 threads, col = lane, each warp computes 4 nodes.
// W transposed into padded smem (conflict-free LDS.128); x read as broadcast LDG.128.
__global__ void __launch_bounds__(256)
k_embed(const float* __restrict__ x, const float* __restrict__ W,
        const float* __restrict__ b, const float* __restrict__ lw,
        const float* __restrict__ lb, float* __restrict__ out) {
    __shared__ float sWT[CC][FIN + 4];   // [col][k], padded
    int tid = threadIdx.x;
    for (int i = tid; i < FIN * CC; i += 256) {
        int k = i >> 5, col = i & 31;
        sWT[col][k] = W[i];              // W[k*CC+col]
    }
    __syncthreads();
    int lane = tid & 31;
    int warp = tid >> 5;
    int n0 = blockIdx.x * 32 + warp * 4;

    float bv = b[lane];
    float acc0 = bv, acc1 = bv, acc2 = bv, acc3 = bv;
    bool ok0 = n0 + 0 < NN, ok1 = n0 + 1 < NN, ok2 = n0 + 2 < NN, ok3 = n0 + 3 < NN;
    const float4* x0 = (const float4*)(x + (size_t)(n0 + 0) * FIN);
    const float4* x1 = (const float4*)(x + (size_t)(n0 + 1) * FIN);
    const float4* x2 = (const float4*)(x + (size_t)(n0 + 2) * FIN);
    const float4* x3 = (const float4*)(x + (size_t)(n0 + 3) * FIN);

    #pragma unroll 4
    for (int kq = 0; kq < FIN / 4; kq++) {
        float4 w4 = *(const float4*)&sWT[lane][kq * 4];
        if (ok0) { float4 v = __ldg(&x0[kq]); acc0 += v.x*w4.x + v.y*w4.y + v.z*w4.z + v.w*w4.w; }
        if (ok1) { float4 v = __ldg(&x1[kq]); acc1 += v.x*w4.x + v.y*w4.y + v.z*w4.z + v.w*w4.w; }
        if (ok2) { float4 v = __ldg(&x2[kq]); acc2 += v.x*w4.x + v.y*w4.y + v.z*w4.z + v.w*w4.w; }
        if (ok3) { float4 v = __ldg(&x3[kq]); acc3 += v.x*w4.x + v.y*w4.y + v.z*w4.z + v.w*w4.w; }
    }

    float lwv = lw[lane], lbv = lb[lane];
    float accs[4] = {acc0, acc1, acc2, acc3};
    #pragma unroll
    for (int m = 0; m < 4; m++) {
        int n = n0 + m;
        if (n >= NN) break;   // warp-uniform
        float a = accs[m];
        float mu = wsum(a) * (1.0f / CC);
        float c = a - mu;
        float var = wsum(c * c) * (1.0f / CC);
        float y = c * rsqrtf(var + LEPS) * lwv + lbv;
        y = fmaxf(y, 0.0f);
        d_h[n * CC + lane] = y;
        out[n * CC + lane] = y;   // JK running max init
    }
}

// ---------------- K2: xl = h@Wl+bl ; xr = h@Wr+br ----------------
// 128 threads: thread owns output col tid with weight columns in registers; 32 nodes/block
__global__ void k_linlr(const float* __restrict__ Wl, const float* __restrict__ bl,
                        const float* __restrict__ Wr, const float* __restrict__ br) {
    __shared__ float4 sh4[32 * 8];   // 32 nodes x 32 feats
    int tid = threadIdx.x;
    float rWl[CC], rWr[CC];
    #pragma unroll
    for (int k = 0; k < CC; k++) {
        rWl[k] = Wl[k * HCC + tid];
        rWr[k] = Wr[k * HCC + tid];
    }
    int base = blockIdx.x * 32;
    for (int i = tid; i < 32 * 8; i += 128) {
        int n = base + (i >> 3);
        sh4[i] = (n < NN) ? *(const float4*)&d_h[n * CC + (i & 7) * 4]
                          : make_float4(0.f, 0.f, 0.f, 0.f);
    }
    __syncthreads();
    float blv = bl[tid], brv = br[tid];
    for (int j = 0; j < 32; j++) {
        int n = base + j;
        if (n >= NN) break;
        float al = blv, ar = brv;
        #pragma unroll
        for (int k4 = 0; k4 < 8; k4++) {
            float4 h4 = sh4[j * 8 + k4];
            al += h4.x * rWl[k4 * 4 + 0]; ar += h4.x * rWr[k4 * 4 + 0];
            al += h4.y * rWl[k4 * 4 + 1]; ar += h4.y * rWr[k4 * 4 + 1];
            al += h4.z * rWl[k4 * 4 + 2]; ar += h4.z * rWr[k4 * 4 + 2];
            al += h4.w * rWl[k4 * 4 + 3]; ar += h4.w * rWr[k4 * 4 + 3];
        }
        d_xl[n * HCC + tid] = al;
        d_xr[n * HCC + tid] = ar;
    }
}

// ---------------- K3: fused GATv2 aggregation + graph-LN reduction ----------------
// warp per dst node; fixed-reference softmax (self logit p).
// Pairwise edge processing with manually interleaved shfl/exp chains (2 chains in
// flight per warp despite in-order issue) + depth-2 PAIR prefetch (4 gathers in flight).
__global__ void k_gat(const float* __restrict__ We, const float* __restrict__ att,
                      const float* __restrict__ gb) {
    int tid = threadIdx.x;
    int lane = tid & 31;
    int w = tid >> 5;
    int n = blockIdx.x * 8 + w;

    float4 xr4  = *(const float4*)&d_xr[(size_t)n * HCC + lane * 4];
    float4 xls  = *(const float4*)&d_xl[(size_t)n * HCC + lane * 4];
    float4 att4 = *(const float4*)&att[lane * 4];
    float4 We4  = *(const float4*)&We[lane * 4];

    int beg = __ldg(&d_rowoff[n]), end = __ldg(&d_rowoff[n + 1]);

    // prefetch current pair + next pair (scalar named regs, no arrays)
    int2 ec0 = make_int2(0, 0), ec1 = ec0, en0 = ec0, en1 = ec0;
    float4 xc0 = make_float4(0.f, 0.f, 0.f, 0.f), xc1 = xc0, xn0 = xc0, xn1 = xc0;
    if (beg < end)     { ec0 = __ldg(&d_csr[beg]);     xc0 = *(const float4*)&d_xl[(size_t)ec0.x * HCC + lane * 4]; }
    if (beg + 1 < end) { ec1 = __ldg(&d_csr[beg + 1]); xc1 = *(const float4*)&d_xl[(size_t)ec1.x * HCC + lane * 4]; }
    if (beg + 2 < end) { en0 = __ldg(&d_csr[beg + 2]); xn0 = *(const float4*)&d_xl[(size_t)en0.x * HCC + lane * 4]; }
    if (beg + 3 < end) { en1 = __ldg(&d_csr[beg + 3]); xn1 = *(const float4*)&d_xl[(size_t)en1.x * HCC + lane * 4]; }

    // self loop logit p (edge_attr = 0) — overlaps the in-flight gathers
    float p;
    {
        float zx = lrelu(xls.x + xr4.x);
        float zy = lrelu(xls.y + xr4.y);
        float zz = lrelu(xls.z + xr4.z);
        float zw = lrelu(xls.w + xr4.w);
        p = zx * att4.x + zy * att4.y + zz * att4.z + zw * att4.w;
        p += __shfl_xor_sync(0xFFFFFFFFu, p, 1);
        p += __shfl_xor_sync(0xFFFFFFFFu, p, 2);
        p += __shfl_xor_sync(0xFFFFFFFFu, p, 4);
    }
    float s = 1.0f;       // exp(p-p)
    float4 acc = xls;     // self message

    int k = beg;
    for (; k + 1 < end; k += 2) {
        int2 a0 = ec0, a1 = ec1;
        float4 b0 = xc0, b1 = xc1;
        ec0 = en0; xc0 = xn0;
        ec1 = en1; xc1 = xn1;
        if (k + 4 < end) { en0 = __ldg(&d_csr[k + 4]); xn0 = *(const float4*)&d_xl[(size_t)en0.x * HCC + lane * 4]; }
        if (k + 5 < end) { en1 = __ldg(&d_csr[k + 5]); xn1 = *(const float4*)&d_xl[(size_t)en1.x * HCC + lane * 4]; }

        float ea0 = __int_as_float(a0.y);
        float ea1 = __int_as_float(a1.y);
        // two independent logit chains, interleaved in program order
        float q0 = lrelu(b0.x + xr4.x + ea0 * We4.x) * att4.x
                 + lrelu(b0.y + xr4.y + ea0 * We4.y) * att4.y
                 + lrelu(b0.z + xr4.z + ea0 * We4.z) * att4.z
                 + lrelu(b0.w + xr4.w + ea0 * We4.w) * att4.w;
        float q1 = lrelu(b1.x + xr4.x + ea1 * We4.x) * att4.x
                 + lrelu(b1.y + xr4.y + ea1 * We4.y) * att4.y
                 + lrelu(b1.z + xr4.z + ea1 * We4.z) * att4.z
                 + lrelu(b1.w + xr4.w + ea1 * We4.w) * att4.w;
        q0 += __shfl_xor_sync(0xFFFFFFFFu, q0, 1);
        q1 += __shfl_xor_sync(0xFFFFFFFFu, q1, 1);
        q0 += __shfl_xor_sync(0xFFFFFFFFu, q0, 2);
        q1 += __shfl_xor_sync(0xFFFFFFFFu, q1, 2);
        q0 += __shfl_xor_sync(0xFFFFFFFFu, q0, 4);
        q1 += __shfl_xor_sync(0xFFFFFFFFu, q1, 4);
        float ex0 = __expf(q0 - p);
        float ex1 = __expf(q1 - p);
        s += ex0;
        acc.x += ex0 * b0.x; acc.y += ex0 * b0.y; acc.z += ex0 * b0.z; acc.w += ex0 * b0.w;
        s += ex1;
        acc.x += ex1 * b1.x; acc.y += ex1 * b1.y; acc.z += ex1 * b1.z; acc.w += ex1 * b1.w;
    }
    if (k < end) {   // odd leftover sits in ec0/xc0
        float ea0 = __int_as_float(ec0.y);
        float q0 = lrelu(xc0.x + xr4.x + ea0 * We4.x) * att4.x
                 + lrelu(xc0.y + xr4.y + ea0 * We4.y) * att4.y
                 + lrelu(xc0.z + xr4.z + ea0 * We4.z) * att4.z
                 + lrelu(xc0.w + xr4.w + ea0 * We4.w) * att4.w;
        q0 += __shfl_xor_sync(0xFFFFFFFFu, q0, 1);
        q0 += __shfl_xor_sync(0xFFFFFFFFu, q0, 2);
        q0 += __shfl_xor_sync(0xFFFFFFFFu, q0, 4);
        float ex0 = __expf(q0 - p);
        s += ex0;
        acc.x += ex0 * xc0.x; acc.y += ex0 * xc0.y; acc.z += ex0 * xc0.z; acc.w += ex0 * xc0.w;
    }
    float inv = 1.0f / s;
    float4 o;
    o.x = acc.x * inv; o.y = acc.y * inv; o.z = acc.z * inv; o.w = acc.w * inv;
    *(float4*)&d_gat[(size_t)n * HCC + lane * 4] = o;

    // ---- fused graph-LN reduction (over o + gb) ----
    float4 gb4 = *(const float4*)&gb[lane * 4];
    float vx = o.x + gb4.x, vy = o.y + gb4.y, vz = o.z + gb4.z, vw = o.w + gb4.w;
    double s0 = (double)vx + (double)vy + (double)vz + (double)vw;
    double s1 = (double)vx * vx + (double)vy * vy + (double)vz * vz + (double)vw * vw;
    #pragma unroll
    for (int off = 16; off; off >>= 1) {
        s0 += __shfl_xor_sync(0xFFFFFFFFu, s0, off);
        s1 += __shfl_xor_sync(0xFFFFFFFFu, s1, off);
    }
    __shared__ double sh0[8], sh1[8];
    if (lane == 0) { sh0[w] = s0; sh1[w] = s1; }
    __syncthreads();
    if (w == 0) {
        s0 = (lane < 8) ? sh0[lane] : 0.0;
        s1 = (lane < 8) ? sh1[lane] : 0.0;
        #pragma unroll
        for (int off = 4; off; off >>= 1) {
            s0 += __shfl_xor_sync(0xFFFFFFFFu, s0, off);
            s1 += __shfl_xor_sync(0xFFFFFFFFu, s1, off);
        }
        if (lane == 0) {
            atomicAdd(&d_red[0], s0);
            atomicAdd(&d_red[1], s1);
            __threadfence();
            unsigned int t = atomicAdd(&d_ctr, 1u);
            if (t == gridDim.x - 1) {
                double inv2 = 1.0 / ((double)NN * (double)HCC);
                double mu = d_red[0] * inv2;
                double var = d_red[1] * inv2 - mu * mu;
                d_stats[0] = (float)mu;
                d_stats[1] = (float)(1.0 / sqrt(var + 1e-5));
                d_red[0] = 0.0;
                d_red[1] = 0.0;
                d_ctr = 0u;
            }
        }
    }
}

// ---------------- K8: graph-LN apply + ReLU + 128->32 GEMM + node LN + ReLU + JK max ----------------
__global__ void k_lin2(const float* __restrict__ gb, const float* __restrict__ l1w,
                       const float* __restrict__ l1b, const float* __restrict__ lw,
                       const float* __restrict__ lb, const float* __restrict__ l2w,
                       const float* __restrict__ l2b, float* __restrict__ out) {
    __shared__ float s_lw[HCC * CC];   // 16 KB
    int tid = threadIdx.x;
    for (int i = tid; i < HCC * CC; i += blockDim.x) s_lw[i] = lw[i];
    __syncthreads();
    int lane = tid & 31;
    int n = blockIdx.x * (blockDim.x >> 5) + (tid >> 5);
    if (n >= NN) return;
    float mu = d_stats[0], rstd = d_stats[1];
    float4 g4  = *(const float4*)&d_gat[(size_t)n * HCC + lane * 4];
    float4 gb4 = *(const float4*)&gb[lane * 4];
    float4 w14 = *(const float4*)&l1w[lane * 4];
    float4 b14 = *(const float4*)&l1b[lane * 4];
    float4 v4;
    v4.x = fmaxf((g4.x + gb4.x - mu) * rstd * w14.x + b14.x, 0.0f);
    v4.y = fmaxf((g4.y + gb4.y - mu) * rstd * w14.y + b14.y, 0.0f);
    v4.z = fmaxf((g4.z + gb4.z - mu) * rstd * w14.z + b14.z, 0.0f);
    v4.w = fmaxf((g4.w + gb4.w - mu) * rstd * w14.w + b14.w, 0.0f);
    float acc = lb[lane];
    #pragma unroll
    for (int j = 0; j < 32; j++) {
        float vx = __shfl_sync(0xFFFFFFFFu, v4.x, j);
        float vy = __shfl_sync(0xFFFFFFFFu, v4.y, j);
        float vz = __shfl_sync(0xFFFFFFFFu, v4.z, j);
        float vw = __shfl_sync(0xFFFFFFFFu, v4.w, j);
        int k = j * 4;
        acc += vx * s_lw[k * CC + lane];
        acc += vy * s_lw[(k + 1) * CC + lane];
        acc += vz * s_lw[(k + 2) * CC + lane];
        acc += vw * s_lw[(k + 3) * CC + lane];
    }
    float m2 = wsum(acc) * (1.0f / CC);
    float c = acc - m2;
    float var = wsum(c * c) * (1.0f / CC);
    float y = c * rsqrtf(var + LEPS) * l2w[lane] + l2b[lane];
    y = fmaxf(y, 0.0f);
    d_h[n * CC + lane] = y;
    out[n * CC + lane] = fmaxf(out[n * CC + lane], y);   // JK max
}

// ---------------- host ----------------
extern "C" void kernel_launch(void* const* d_in, const int* in_sizes, int n_in,
                              void* d_out, int out_size) {
    const float* x     = (const float*)d_in[0];
    const int*   ei    = (const int*)d_in[1];
    const float* ea    = (const float*)d_in[2];
    const float* W_emb = (const float*)d_in[3];
    const float* b_emb = (const float*)d_in[4];
    const float* ln0w  = (const float*)d_in[5];
    const float* ln0b  = (const float*)d_in[6];
    const float* Wl    = (const float*)d_in[7];
    const float* bl    = (const float*)d_in[8];
    const float* Wr    = (const float*)d_in[9];
    const float* br    = (const float*)d_in[10];
    const float* We    = (const float*)d_in[11];
    const float* att   = (const float*)d_in[12];
    const float* gatb  = (const float*)d_in[13];
    const float* ln1w  = (const float*)d_in[14];
    const float* ln1b  = (const float*)d_in[15];
    const float* linw  = (const float*)d_in[16];
    const float* linb  = (const float*)d_in[17];
    const float* ln2w  = (const float*)d_in[18];
    const float* ln2b  = (const float*)d_in[19];

    const int* src = ei;
    const int* dst = ei + EE;
    float* out = (float*)d_out;

    const int gatBlocks   = NN / 8;            // 6250, exact
    const int embedBlocks = (NN + 31) / 32;    // 1563

    // CSR build: 3 launches; k_scan re-zeros d_cnt for graph replay
    k_hist<<<(EE + 255) / 256, 256>>>(dst);
    k_scan<<<1, 1024>>>();
    k_scatter<<<(EE + 255) / 256, 256>>>(src, dst, ea);

    k_embed<<<embedBlocks, 256>>>(x, W_emb, b_emb, ln0w, ln0b, out);

    for (int l = 0; l < 2; l++) {
        const float* Wl_l  = Wl + l * CC * HCC;
        const float* bl_l  = bl + l * HCC;
        const float* Wr_l  = Wr + l * CC * HCC;
        const float* br_l  = br + l * HCC;
        const float* We_l  = We + l * HCC;
        const float* att_l = att + l * HH * CC;
        const float* gb_l  = gatb + l * HCC;
        const float* l1w_l = ln1w + l * HCC;
        const float* l1b_l = ln1b + l * HCC;
        const float* lw_l  = linw + l * HCC * CC;
        const float* lb_l  = linb + l * CC;
        const float* l2w_l = ln2w + l * CC;
        const float* l2b_l = ln2b + l * CC;

        k_linlr<<<(NN + 31) / 32, 128>>>(Wl_l, bl_l, Wr_l, br_l);
        k_gat<<<gatBlocks, 256>>>(We_l, att_l, gb_l);
        k_lin2<<<gatBlocks, 256>>>(gb_l, l1w_l, l1b_l, lw_l, lb_l, l2w_l, l2b_l, out);
    }
}

// round 16
// speedup vs baseline: 2.6577x; 1.5800x over previous
#include <cuda_runtime.h>
#include <math.h>

#define NN 50000
#define EE 800000
#define FIN 256
#define CC 32
#define HH 4
#define HCC 128
#define LEPS 1e-5f
#define SLOPE 0.2f

// ---------------- scratch (no allocs allowed) ----------------
__device__ float d_h[NN * CC];        // current node features
__device__ float d_xl[NN * HCC];      // lin_l(h)
__device__ float d_xr[NN * HCC];      // lin_r(h)
__device__ float d_gat[NN * HCC];     // GAT aggregation output
__device__ double d_red[2];           // global sum / sumsq (self-resetting)
__device__ unsigned int d_ctr;        // block-completion counter (self-resetting)
__device__ float d_stats[2];          // mu, rstd for graph-LN
// CSR by destination
__device__ int  d_cnt[NN];
__device__ int  d_rowoff[NN + 1];
__device__ int  d_cursor[NN];
__device__ int2 d_csr[EE];            // (src, ea as bits)

// ---------------- helpers ----------------
__device__ __forceinline__ float wsum(float v) {
    #pragma unroll
    for (int o = 16; o; o >>= 1) v += __shfl_xor_sync(0xFFFFFFFFu, v, o);
    return v;
}
__device__ __forceinline__ float lrelu(float z) {
    return z > 0.0f ? z : SLOPE * z;
}

// ---------------- CSR build ----------------
__global__ void k_histzero() {
    int i = blockIdx.x * blockDim.x + threadIdx.x;
    if (i < NN) d_cnt[i] = 0;
}
__global__ void k_hist(const int* __restrict__ dst) {
    int e = blockIdx.x * blockDim.x + threadIdx.x;
    if (e < EE) atomicAdd(&d_cnt[dst[e]], 1);
}
// single block, 1024 threads: exclusive scan of d_cnt -> d_rowoff, d_cursor
__global__ void k_scan() {
    __shared__ int wsum_ex[32];
    __shared__ int s_total;
    int lane = threadIdx.x & 31, wid = threadIdx.x >> 5;
    int carry = 0;
    const int CH = (NN + 1023) / 1024;
    for (int c = 0; c < CH; c++) {
        int i = c * 1024 + threadIdx.x;
        int v = (i < NN) ? d_cnt[i] : 0;
        int inc = v;
        #pragma unroll
        for (int o = 1; o < 32; o <<= 1) {
            int t = __shfl_up_sync(0xFFFFFFFFu, inc, o);
            if (lane >= o) inc += t;
        }
        if (lane == 31) wsum_ex[wid] = inc;
        __syncthreads();
        if (wid == 0) {
            int w = wsum_ex[lane];
            int wi = w;
            #pragma unroll
            for (int o = 1; o < 32; o <<= 1) {
                int t = __shfl_up_sync(0xFFFFFFFFu, wi, o);
                if (lane >= o) wi += t;
            }
            wsum_ex[lane] = wi - w;
            if (lane == 31) s_total = wi;
        }
        __syncthreads();
        int excl = carry + wsum_ex[wid] + (inc - v);
        if (i < NN) { d_rowoff[i] = excl; d_cursor[i] = excl; }
        carry += s_total;
        __syncthreads();
    }
    if (threadIdx.x == 0) d_rowoff[NN] = EE;
}
__global__ void k_scatter(const int* __restrict__ src, const int* __restrict__ dst,
                          const float* __restrict__ ea) {
    int e = blockIdx.x * blockDim.x + threadIdx.x;
    if (e >= EE) return;
    int d = dst[e];
    int pos = atomicAdd(&d_cursor[d], 1);
    d_csr[pos] = make_int2(src[e], __float_as_int(ea[e]));
}

// ---------------- K1: embed GEMM + node LN + ReLU + JK init ----------------
// 256 threads = 8 warps; warp handles 4 nodes sequentially.
// x-row staged in smem via coalesced LDG.128/STS.128, read back as broadcast LDS.128.
// W transposed+padded in smem. Zero shuffles in mainloop; 128 LDS.128 per node.
__global__ void __launch_bounds__(256)
k_embed(const float* __restrict__ x, const float* __restrict__ W,
        const float* __restrict__ b, const float* __restrict__ lw,
        const float* __restrict__ lb, float* __restrict__ out) {
    __shared__ float sWT[CC][FIN + 4];   // [col][k], padded (33 KB)
    __shared__ float sX[8][FIN];         // per-warp x-row buffer (8 KB)
    int tid = threadIdx.x;
    for (int i = tid; i < FIN * CC; i += 256) {
        int k = i >> 5, col = i & 31;
        sWT[col][k] = W[i];              // W[k*CC+col]
    }
    __syncthreads();
    int lane = tid & 31;
    int w = tid >> 5;
    int n0 = blockIdx.x * 32 + w * 4;

    float bv = b[lane], lwv = lw[lane], lbv = lb[lane];

    // prefetch first row into registers (coalesced: lane covers 2 float4 slices)
    float4 rA = make_float4(0.f, 0.f, 0.f, 0.f), rB = rA;
    if (n0 < NN) {
        const float* row = x + (size_t)n0 * FIN;
        rA = __ldg((const float4*)(row) + lane);
        rB = __ldg((const float4*)(row) + 32 + lane);
    }

    #pragma unroll
    for (int m = 0; m < 4; m++) {
        int n = n0 + m;
        if (n >= NN) break;   // warp-uniform
        // stage current row
        *(float4*)&sX[w][lane * 4] = rA;
        *(float4*)&sX[w][128 + lane * 4] = rB;
        __syncwarp();
        // prefetch next row (overlaps compute)
        if (m < 3 && n + 1 < NN) {
            const float* row = x + (size_t)(n + 1) * FIN;
            rA = __ldg((const float4*)(row) + lane);
            rB = __ldg((const float4*)(row) + 32 + lane);
        }
        // GEMM: acc[col=lane] = sum_k x[k] * W[k][lane]
        float acc = bv;
        #pragma unroll 8
        for (int kq = 0; kq < FIN / 4; kq++) {
            float4 xv = *(const float4*)&sX[w][kq * 4];       // broadcast
            float4 wv = *(const float4*)&sWT[lane][kq * 4];   // conflict-free
            acc += xv.x * wv.x + xv.y * wv.y + xv.z * wv.z + xv.w * wv.w;
        }
        __syncwarp();   // sX reads done before next iteration's STS
        // node LN + ReLU
        float mu = wsum(acc) * (1.0f / CC);
        float c = acc - mu;
        float var = wsum(c * c) * (1.0f / CC);
        float y = c * rsqrtf(var + LEPS) * lwv + lbv;
        y = fmaxf(y, 0.0f);
        d_h[n * CC + lane] = y;
        out[n * CC + lane] = y;   // JK running max init
    }
}

// ---------------- K2: xl = h@Wl+bl ; xr = h@Wr+br ----------------
// 128 threads: thread owns output col tid with weight columns in registers; 32 nodes/block
__global__ void k_linlr(const float* __restrict__ Wl, const float* __restrict__ bl,
                        const float* __restrict__ Wr, const float* __restrict__ br) {
    __shared__ float4 sh4[32 * 8];   // 32 nodes x 32 feats
    int tid = threadIdx.x;
    float rWl[CC], rWr[CC];
    #pragma unroll
    for (int k = 0; k < CC; k++) {
        rWl[k] = Wl[k * HCC + tid];
        rWr[k] = Wr[k * HCC + tid];
    }
    int base = blockIdx.x * 32;
    for (int i = tid; i < 32 * 8; i += 128) {
        int n = base + (i >> 3);
        sh4[i] = (n < NN) ? *(const float4*)&d_h[n * CC + (i & 7) * 4]
                          : make_float4(0.f, 0.f, 0.f, 0.f);
    }
    __syncthreads();
    float blv = bl[tid], brv = br[tid];
    for (int j = 0; j < 32; j++) {
        int n = base + j;
        if (n >= NN) break;
        float al = blv, ar = brv;
        #pragma unroll
        for (int k4 = 0; k4 < 8; k4++) {
            float4 h4 = sh4[j * 8 + k4];
            al += h4.x * rWl[k4 * 4 + 0]; ar += h4.x * rWr[k4 * 4 + 0];
            al += h4.y * rWl[k4 * 4 + 1]; ar += h4.y * rWr[k4 * 4 + 1];
            al += h4.z * rWl[k4 * 4 + 2]; ar += h4.z * rWr[k4 * 4 + 2];
            al += h4.w * rWl[k4 * 4 + 3]; ar += h4.w * rWr[k4 * 4 + 3];
        }
        d_xl[n * HCC + tid] = al;
        d_xr[n * HCC + tid] = ar;
    }
}

// ---------------- K3: fused GATv2 aggregation + graph-LN reduction ----------------
// warp per dst node (grid exactly NN/8 blocks of 256 => no tail warps).
// Softmax stabilized with the CONSTANT self-loop logit p: alpha = exp(q-p)/sum.
// Depth-2 rotating-register software pipeline (the proven R6 configuration).
__global__ void k_gat(const float* __restrict__ We, const float* __restrict__ att,
                      const float* __restrict__ gb) {
    int tid = threadIdx.x;
    int lane = tid & 31;
    int w = tid >> 5;
    int n = blockIdx.x * 8 + w;

    float4 xr4  = *(const float4*)&d_xr[(size_t)n * HCC + lane * 4];
    float4 xls  = *(const float4*)&d_xl[(size_t)n * HCC + lane * 4];
    float4 att4 = *(const float4*)&att[lane * 4];
    float4 We4  = *(const float4*)&We[lane * 4];

    // self loop logit p (edge_attr = 0)
    float p;
    {
        float zx = lrelu(xls.x + xr4.x);
        float zy = lrelu(xls.y + xr4.y);
        float zz = lrelu(xls.z + xr4.z);
        float zw = lrelu(xls.w + xr4.w);
        p = zx * att4.x + zy * att4.y + zz * att4.z + zw * att4.w;
        p += __shfl_xor_sync(0xFFFFFFFFu, p, 1);
        p += __shfl_xor_sync(0xFFFFFFFFu, p, 2);
        p += __shfl_xor_sync(0xFFFFFFFFu, p, 4);
    }
    float s = 1.0f;       // exp(p-p)
    float4 acc = xls;     // self message

    int beg = __ldg(&d_rowoff[n]), end = __ldg(&d_rowoff[n + 1]);

    // depth-2 software pipeline
    int2 e0 = make_int2(0, 0), e1 = make_int2(0, 0);
    float4 x0 = make_float4(0.f, 0.f, 0.f, 0.f), x1 = x0;
    if (beg < end) {
        e0 = __ldg(&d_csr[beg]);
        x0 = *(const float4*)&d_xl[(size_t)e0.x * HCC + lane * 4];
    }
    if (beg + 1 < end) {
        e1 = __ldg(&d_csr[beg + 1]);
        x1 = *(const float4*)&d_xl[(size_t)e1.x * HCC + lane * 4];
    }
    for (int k = beg; k < end; k++) {
        int2 ec = e0;
        float4 xc = x0;
        e0 = e1; x0 = x1;
        if (k + 2 < end) {
            e1 = __ldg(&d_csr[k + 2]);
            x1 = *(const float4*)&d_xl[(size_t)e1.x * HCC + lane * 4];
        }
        float eaf = __int_as_float(ec.y);
        float zx = lrelu(xc.x + xr4.x + eaf * We4.x);
        float zy = lrelu(xc.y + xr4.y + eaf * We4.y);
        float zz = lrelu(xc.z + xr4.z + eaf * We4.z);
        float zw = lrelu(xc.w + xr4.w + eaf * We4.w);
        float q = zx * att4.x + zy * att4.y + zz * att4.z + zw * att4.w;
        q += __shfl_xor_sync(0xFFFFFFFFu, q, 1);
        q += __shfl_xor_sync(0xFFFFFFFFu, q, 2);
        q += __shfl_xor_sync(0xFFFFFFFFu, q, 4);
        float ex = __expf(q - p);
        s += ex;
        acc.x += ex * xc.x;
        acc.y += ex * xc.y;
        acc.z += ex * xc.z;
        acc.w += ex * xc.w;
    }
    float inv = 1.0f / s;
    float4 o;
    o.x = acc.x * inv; o.y = acc.y * inv; o.z = acc.z * inv; o.w = acc.w * inv;
    *(float4*)&d_gat[(size_t)n * HCC + lane * 4] = o;

    // ---- fused graph-LN reduction (over o + gb) ----
    float4 gb4 = *(const float4*)&gb[lane * 4];
    float vx = o.x + gb4.x, vy = o.y + gb4.y, vz = o.z + gb4.z, vw = o.w + gb4.w;
    double s0 = (double)vx + (double)vy + (double)vz + (double)vw;
    double s1 = (double)vx * vx + (double)vy * vy + (double)vz * vz + (double)vw * vw;
    #pragma unroll
    for (int off = 16; off; off >>= 1) {
        s0 += __shfl_xor_sync(0xFFFFFFFFu, s0, off);
        s1 += __shfl_xor_sync(0xFFFFFFFFu, s1, off);
    }
    __shared__ double sh0[8], sh1[8];
    if (lane == 0) { sh0[w] = s0; sh1[w] = s1; }
    __syncthreads();
    if (w == 0) {
        s0 = (lane < 8) ? sh0[lane] : 0.0;
        s1 = (lane < 8) ? sh1[lane] : 0.0;
        #pragma unroll
        for (int off = 4; off; off >>= 1) {
            s0 += __shfl_xor_sync(0xFFFFFFFFu, s0, off);
            s1 += __shfl_xor_sync(0xFFFFFFFFu, s1, off);
        }
        if (lane == 0) {
            atomicAdd(&d_red[0], s0);
            atomicAdd(&d_red[1], s1);
            __threadfence();
            unsigned int t = atomicAdd(&d_ctr, 1u);
            if (t == gridDim.x - 1) {
                double inv2 = 1.0 / ((double)NN * (double)HCC);
                double mu = d_red[0] * inv2;
                double var = d_red[1] * inv2 - mu * mu;
                d_stats[0] = (float)mu;
                d_stats[1] = (float)(1.0 / sqrt(var + 1e-5));
                d_red[0] = 0.0;      // self-reset for next launch / replay
                d_red[1] = 0.0;
                d_ctr = 0u;
            }
        }
    }
}

// ---------------- K8: graph-LN apply + ReLU + 128->32 GEMM + node LN + ReLU + JK max ----------------
__global__ void k_lin2(const float* __restrict__ gb, const float* __restrict__ l1w,
                       const float* __restrict__ l1b, const float* __restrict__ lw,
                       const float* __restrict__ lb, const float* __restrict__ l2w,
                       const float* __restrict__ l2b, float* __restrict__ out) {
    __shared__ float s_lw[HCC * CC];   // 16 KB
    int tid = threadIdx.x;
    for (int i = tid; i < HCC * CC; i += blockDim.x) s_lw[i] = lw[i];
    __syncthreads();
    int lane = tid & 31;
    int n = blockIdx.x * (blockDim.x >> 5) + (tid >> 5);
    if (n >= NN) return;
    float mu = d_stats[0], rstd = d_stats[1];
    float4 g4  = *(const float4*)&d_gat[(size_t)n * HCC + lane * 4];
    float4 gb4 = *(const float4*)&gb[lane * 4];
    float4 w14 = *(const float4*)&l1w[lane * 4];
    float4 b14 = *(const float4*)&l1b[lane * 4];
    float4 v4;
    v4.x = fmaxf((g4.x + gb4.x - mu) * rstd * w14.x + b14.x, 0.0f);
    v4.y = fmaxf((g4.y + gb4.y - mu) * rstd * w14.y + b14.y, 0.0f);
    v4.z = fmaxf((g4.z + gb4.z - mu) * rstd * w14.z + b14.z, 0.0f);
    v4.w = fmaxf((g4.w + gb4.w - mu) * rstd * w14.w + b14.w, 0.0f);
    float acc = lb[lane];
    #pragma unroll
    for (int j = 0; j < 32; j++) {
        float vx = __shfl_sync(0xFFFFFFFFu, v4.x, j);
        float vy = __shfl_sync(0xFFFFFFFFu, v4.y, j);
        float vz = __shfl_sync(0xFFFFFFFFu, v4.z, j);
        float vw = __shfl_sync(0xFFFFFFFFu, v4.w, j);
        int k = j * 4;
        acc += vx * s_lw[k * CC + lane];
        acc += vy * s_lw[(k + 1) * CC + lane];
        acc += vz * s_lw[(k + 2) * CC + lane];
        acc += vw * s_lw[(k + 3) * CC + lane];
    }
    float m2 = wsum(acc) * (1.0f / CC);
    float c = acc - m2;
    float var = wsum(c * c) * (1.0f / CC);
    float y = c * rsqrtf(var + LEPS) * l2w[lane] + l2b[lane];
    y = fmaxf(y, 0.0f);
    d_h[n * CC + lane] = y;
    out[n * CC + lane] = fmaxf(out[n * CC + lane], y);   // JK max
}

// ---------------- host ----------------
extern "C" void kernel_launch(void* const* d_in, const int* in_sizes, int n_in,
                              void* d_out, int out_size) {
    const float* x     = (const float*)d_in[0];
    const int*   ei    = (const int*)d_in[1];
    const float* ea    = (const float*)d_in[2];
    const float* W_emb = (const float*)d_in[3];
    const float* b_emb = (const float*)d_in[4];
    const float* ln0w  = (const float*)d_in[5];
    const float* ln0b  = (const float*)d_in[6];
    const float* Wl    = (const float*)d_in[7];
    const float* bl    = (const float*)d_in[8];
    const float* Wr    = (const float*)d_in[9];
    const float* br    = (const float*)d_in[10];
    const float* We    = (const float*)d_in[11];
    const float* att   = (const float*)d_in[12];
    const float* gatb  = (const float*)d_in[13];
    const float* ln1w  = (const float*)d_in[14];
    const float* ln1b  = (const float*)d_in[15];
    const float* linw  = (const float*)d_in[16];
    const float* linb  = (const float*)d_in[17];
    const float* ln2w  = (const float*)d_in[18];
    const float* ln2b  = (const float*)d_in[19];

    const int* src = ei;
    const int* dst = ei + EE;
    float* out = (float*)d_out;

    const int gatBlocks   = NN / 8;            // 6250, exact
    const int embedBlocks = (NN + 31) / 32;    // 1563 (warp does 4 nodes)

    // CSR build (reused by both layers) — exact R6-best configuration
    k_histzero<<<(NN + 255) / 256, 256>>>();
    k_hist<<<(EE + 255) / 256, 256>>>(dst);
    k_scan<<<1, 1024>>>();
    k_scatter<<<(EE + 255) / 256, 256>>>(src, dst, ea);

    k_embed<<<embedBlocks, 256>>>(x, W_emb, b_emb, ln0w, ln0b, out);

    for (int l = 0; l < 2; l++) {
        const float* Wl_l  = Wl + l * CC * HCC;
        const float* bl_l  = bl + l * HCC;
        const float* Wr_l  = Wr + l * CC * HCC;
        const float* br_l  = br + l * HCC;
        const float* We_l  = We + l * HCC;
        const float* att_l = att + l * HH * CC;
        const float* gb_l  = gatb + l * HCC;
        const float* l1w_l = ln1w + l * HCC;
        const float* l1b_l = ln1b + l * HCC;
        const float* lw_l  = linw + l * HCC * CC;
        const float* lb_l  = linb + l * CC;
        const float* l2w_l = ln2w + l * CC;
        const float* l2b_l = ln2b + l * CC;

        k_linlr<<<(NN + 31) / 32, 128>>>(Wl_l, bl_l, Wr_l, br_l);
        k_gat<<<gatBlocks, 256>>>(We_l, att_l, gb_l);
        k_lin2<<<gatBlocks, 256>>>(gb_l, l1w_l, l1b_l, lw_l, lb_l, l2w_l, l2b_l, out);
    }
}